// round 9
// baseline (speedup 1.0000x reference)
#include <cuda_runtime.h>
#include <cstdint>
#include <cstddef>

#define LOG2E_F 1.4426950408889634f
#define LN2_F   0.6931471805599453f

__device__ __forceinline__ float ex2f_(float x) {
    float y; asm("ex2.approx.ftz.f32 %0, %1;" : "=f"(y) : "f"(x)); return y;
}
__device__ __forceinline__ float lg2f_(float x) {
    float y; asm("lg2.approx.f32 %0, %1;" : "=f"(y) : "f"(x)); return y;
}
__device__ __forceinline__ unsigned long long pk2(float lo, float hi) {
    unsigned long long r; asm("mov.b64 %0, {%1, %2};" : "=l"(r) : "f"(lo), "f"(hi)); return r;
}
__device__ __forceinline__ void upk2(unsigned long long v, float& lo, float& hi) {
    asm("mov.b64 {%0, %1}, %2;" : "=f"(lo), "=f"(hi) : "l"(v));
}
__device__ __forceinline__ void fma2_(unsigned long long& acc, unsigned long long a, unsigned long long b) {
    asm("fma.rn.f32x2 %0, %1, %2, %0;" : "+l"(acc) : "l"(a), "l"(b));
}
__device__ __forceinline__ unsigned long long add2_(unsigned long long a, unsigned long long b) {
    unsigned long long r; asm("add.rn.f32x2 %0, %1, %2;" : "=l"(r) : "l"(a), "l"(b)); return r;
}
__device__ __forceinline__ void nbar_(int id) {
    asm volatile("bar.sync %0, 128;" :: "r"(id) : "memory");
}

// TWO independent batches per CTA, 256 threads. Warps 0-3 run batch 2*bid
// (threads lt=tid&127, column-per-thread), warps 4-7 run batch 2*bid+1.
// Each SMSP hosts ONE warp of EACH batch: two independent serial chains
// (BAR -> LDS -> fma drain -> STS) interleave in the scheduler, filling the
// ~70% idle issue slots measured on all single-recurrence variants (R3-R8).
// The two recurrences are decoupled by NAMED barriers (bar.sync 1/2, 128
// threads) so neither chain ever waits on the other's warps. No reg cap:
// 256 thr @ launch_bounds(256,1) -> 255 regs available (~190 used, no spill
// -- the failure mode of the fused-512-thread R7 attempt).
// Per thread per step: 32 broadcast LDS.128 + 64 fma.rn.f32x2 (8 chains)
// + 0 shuffles + 1 coalesced obs load (4-deep ring) + 1 EX2 + STS.32.
// Linear-domain forward vector; exact power-of-2 renorm every 8 steps
// (publish per-batch block max at t%8==0 via REDUX, fold 2^-e at t%8==1).
__global__ __launch_bounds__(256, 1)
void crf_fwd_kernel(const float* __restrict__ obs,
                    const float* __restrict__ logA,
                    float* __restrict__ out,
                    int T, int B)
{
    constexpr int S = 128;
    __shared__ __align__(16) float v_sm[2][2][S];   // [half][buf][state]
    __shared__ float wm[2][4];
    __shared__ float wsum[2][4];

    const int tid = threadIdx.x;
    const int h   = tid >> 7;          // batch half: 0 or 1
    const int lt  = tid & 127;         // column j within half
    const int wb  = lt >> 5;           // warp index within half (0..3)
    const int bid = 2 * (int)blockIdx.x + h;
    const int b   = (bid < B) ? bid : (B - 1);
    const int nbid = h + 1;            // named barrier id (1 or 2)

    const float* ob = obs + (size_t)b * (size_t)T * S + lt;

    // A[k] = {E[2k][j], E[2k+1][j]}  (column j of exp(logA), i-pair packed)
    unsigned long long A[64];
#pragma unroll
    for (int k = 0; k < 64; ++k) {
        const float ea = logA[(size_t)(2 * k) * S + lt];
        const float eb = logA[(size_t)(2 * k + 1) * S + lt];
        A[k] = pk2(ex2f_(ea * LOG2E_F), ex2f_(eb * LOG2E_F));
    }

    // ---- t = 0 (t%8==0): u = exp(obs[0]) raw; publish per-batch max ----
    const float o0 = ob[0];
    const float u  = ex2f_(o0 * LOG2E_F);
    {
        const int im = __reduce_max_sync(0xffffffffu, __float_as_int(u));
        if ((lt & 31) == 0) wm[h][wb] = __int_as_float(im);
        v_sm[h][0][lt] = u;
    }

    // 4-deep obs prefetch ring: oR[t & 3] holds obs[t].
    float oR[4];
#pragma unroll
    for (int k = 1; k <= 4; ++k)
        oR[k & 3] = (k < T) ? __ldcs(ob + (size_t)k * S) : o0;

    int L = 0;                 // exact accumulated log2 scale (uniform per batch)
    nbar_(nbid);

    // ---- scan t = 1 .. T-1, ONE named barrier per step ----
#pragma unroll 2
    for (int t = 1; t < T; ++t) {
        const int cb = (t - 1) & 1, nb = t & 1;

        const float oc = oR[t & 3];
        if (t + 4 < T) oR[t & 3] = __ldcs(ob + (size_t)(t + 4) * S);

        // observation factor early (MUFU latency hides under the matvec)
        const float p = ex2f_(oc * LOG2E_F);

        // fold previous publish's exact 2^-e every 8th step
        float sc = 1.0f;
        const bool fold = (t & 7) == 1;
        if (fold) {
            const float m = fmaxf(fmaxf(wm[h][0], wm[h][1]), fmaxf(wm[h][2], wm[h][3]));
            const int e = ((__float_as_int(m) >> 23) & 0xFF) - 127;
            L += e;
            sc = __int_as_float((127 - e) << 23);   // exact 2^-e
        }

        // full 128-i dot product: 32 broadcast LDS.128, 8 independent fma2 chains
        const ulonglong2* V = reinterpret_cast<const ulonglong2*>(&v_sm[h][cb][0]);
        unsigned long long c0 = 0ull, c1 = 0ull, c2 = 0ull, c3 = 0ull;
        unsigned long long c4 = 0ull, c5 = 0ull, c6 = 0ull, c7 = 0ull;
#pragma unroll
        for (int k = 0; k < 8; ++k) {
            const ulonglong2 v0 = V[4 * k + 0];
            const ulonglong2 v1 = V[4 * k + 1];
            const ulonglong2 v2 = V[4 * k + 2];
            const ulonglong2 v3 = V[4 * k + 3];
            fma2_(c0, v0.x, A[8 * k + 0]);
            fma2_(c1, v0.y, A[8 * k + 1]);
            fma2_(c2, v1.x, A[8 * k + 2]);
            fma2_(c3, v1.y, A[8 * k + 3]);
            fma2_(c4, v2.x, A[8 * k + 4]);
            fma2_(c5, v2.y, A[8 * k + 5]);
            fma2_(c6, v3.x, A[8 * k + 6]);
            fma2_(c7, v3.y, A[8 * k + 7]);
        }
        const unsigned long long s01 = add2_(c0, c1);
        const unsigned long long s23 = add2_(c2, c3);
        const unsigned long long s45 = add2_(c4, c5);
        const unsigned long long s67 = add2_(c6, c7);
        float lo, hi;
        upk2(add2_(add2_(s01, s23), add2_(s45, s67)), lo, hi);
        const float acc = lo + hi;

        const float un = fold ? acc * (p * sc) : acc * p;

        // write v first; publish per-batch block max every 8th step
        v_sm[h][nb][lt] = un;
        if ((t & 7) == 0) {
            const int im = __reduce_max_sync(0xffffffffu, __float_as_int(un));
            if ((lt & 31) == 0) wm[h][wb] = __int_as_float(im);
        }
        nbar_(nbid);
    }

    // ---- finalize per batch: out[b] = -ln2 * (log2(sum_j v_j) + L) ----
    const int fb = (T - 1) & 1;
    float vv = v_sm[h][fb][lt];
#pragma unroll
    for (int o = 16; o; o >>= 1) vv += __shfl_xor_sync(0xffffffffu, vv, o);
    if ((lt & 31) == 0) wsum[h][wb] = vv;
    nbar_(nbid);
    if (lt == 0 && bid < B) {
        const float s = (wsum[h][0] + wsum[h][1]) + (wsum[h][2] + wsum[h][3]);
        out[b] = -LN2_F * (lg2f_(s) + (float)L);
    }
}

extern "C" void kernel_launch(void* const* d_in, const int* in_sizes, int n_in,
                              void* d_out, int out_size)
{
    const float* obs  = (const float*)d_in[0];   // [B, T, S] f32
    const float* logA = (const float*)d_in[1];   // [S, S]   f32
    float* out = (float*)d_out;                  // [B]      f32

    const int B = out_size;
    const int S = 128;
    const int T = in_sizes[0] / (B * S);

    const int grid = (B + 1) / 2;
    crf_fwd_kernel<<<grid, 256>>>(obs, logA, out, T, B);
}

// round 10
// speedup vs baseline: 1.8706x; 1.8706x over previous
#include <cuda_runtime.h>
#include <cstdint>
#include <cstddef>

#define LOG2E_F 1.4426950408889634f
#define LN2_F   0.6931471805599453f

__device__ __forceinline__ float ex2f_(float x) {
    float y; asm("ex2.approx.ftz.f32 %0, %1;" : "=f"(y) : "f"(x)); return y;
}
__device__ __forceinline__ float lg2f_(float x) {
    float y; asm("lg2.approx.f32 %0, %1;" : "=f"(y) : "f"(x)); return y;
}
__device__ __forceinline__ unsigned long long pk2(float lo, float hi) {
    unsigned long long r; asm("mov.b64 %0, {%1, %2};" : "=l"(r) : "f"(lo), "f"(hi)); return r;
}
__device__ __forceinline__ void upk2(unsigned long long v, float& lo, float& hi) {
    asm("mov.b64 {%0, %1}, %2;" : "=f"(lo), "=f"(hi) : "l"(v));
}
__device__ __forceinline__ void fma2_(unsigned long long& acc, unsigned long long a, unsigned long long b) {
    asm("fma.rn.f32x2 %0, %1, %2, %0;" : "+l"(acc) : "l"(a), "l"(b));
}
__device__ __forceinline__ unsigned long long add2_(unsigned long long a, unsigned long long b) {
    unsigned long long r; asm("add.rn.f32x2 %0, %1, %2;" : "=l"(r) : "l"(a), "l"(b)); return r;
}

// One CTA per batch, 256 threads (8 warps) — the R3 configuration, which is
// the measured optimum of this design family (634 cyc/step; every structural
// variant R4-R9 regressed). Two subtractive changes vs R3:
//  (1) renormalization scale now comes from STATE 0's exponent (one broadcast
//      LDS all threads share) instead of a block-max REDUX+publish — the
//      reference only needs to be uniform, not the max; state ratios are
//      bounded well within fp32 range between 8-step folds.
//  (2) observation ex2 factors are computed one step AHEAD (pipelined in
//      registers), keeping the 16-cyc MUFU latency structurally off the
//      post-barrier critical chain.
// Layout: cp = tid>>2 -> column pair (j0 = 2cp, j0+1); ich = tid&3 ->
// 32-wide "from"-chunk; E = exp(logA) in registers as i-pair packed f32x2;
// per thread per step: 16 broadcast LDS.64 + 32 fma.rn.f32x2 (4 chains)
// + 2 shfl; forward vector linear-domain in double-buffered padded smem;
// exact power-of-2 renorm every 8 steps (fold at t%8==1); ONE __syncthreads
// per step; obs via 4-deep register prefetch ring.
__global__ __launch_bounds__(256, 1)
void crf_fwd_kernel(const float* __restrict__ obs,
                    const float* __restrict__ logA,
                    float* __restrict__ out,
                    int T)
{
    constexpr int S  = 128;
    constexpr int CH = 34;     // chunk stride (floats): 8B-aligned, bank-skewed
    __shared__ __align__(16) float v_sm[2][4 * CH];
    __shared__ float wsum[4];

    const int tid  = threadIdx.x;
    const int b    = blockIdx.x;
    const int cp   = tid >> 2;
    const int ich  = tid & 3;
    const int j0   = cp * 2;
    const int wslot = ((j0 >> 5) * CH) + (j0 & 31);

    const float* ob = obs + (size_t)b * (size_t)T * S + j0;

    // A0[k] = {E[i0+2k][j0],   E[i0+2k+1][j0]}
    // A1[k] = {E[i0+2k][j0+1], E[i0+2k+1][j0+1]},  i0 = 32*ich
    unsigned long long A0[16], A1[16];
#pragma unroll
    for (int k = 0; k < 16; ++k) {
        const int i0 = ich * 32 + 2 * k;
        const float2 ea = *reinterpret_cast<const float2*>(logA + (size_t)i0 * S + j0);
        const float2 eb = *reinterpret_cast<const float2*>(logA + (size_t)(i0 + 1) * S + j0);
        A0[k] = pk2(ex2f_(ea.x * LOG2E_F), ex2f_(eb.x * LOG2E_F));
        A1[k] = pk2(ex2f_(ea.y * LOG2E_F), ex2f_(eb.y * LOG2E_F));
    }

    // ---- t = 0: u = exp(obs[0]) stored raw ----
    const float2 o0 = *reinterpret_cast<const float2*>(ob);
    const float u0 = ex2f_(o0.x * LOG2E_F);
    const float u1 = ex2f_(o0.y * LOG2E_F);
    if (ich == 0) {
        float2 w; w.x = u0; w.y = u1;
        *reinterpret_cast<float2*>(&v_sm[0][wslot]) = w;
    }

    // 4-deep obs prefetch ring: oR[t & 3] holds obs[t].
    float2 oR[4];
#pragma unroll
    for (int k = 1; k <= 4; ++k)
        oR[k & 3] = (k < T) ? __ldcs(reinterpret_cast<const float2*>(ob + (size_t)k * S)) : o0;

    // Pipelined observation factor for step t=1 (computed before the scan).
    float pn0 = ex2f_(oR[1].x * LOG2E_F);
    float pn1 = ex2f_(oR[1].y * LOG2E_F);

    int L = 0;                 // exact accumulated log2 scale (uniform across block)
    __syncthreads();

    // ---- scan t = 1 .. T-1, ONE barrier per step ----
#pragma unroll 4
    for (int t = 1; t < T; ++t) {
        const int cb = (t - 1) & 1, nb = t & 1;

        // current step's observation factors (computed LAST iteration)
        const float p0 = pn0;
        const float p1 = pn1;

        // prefetch obs[t+4]; compute NEXT step's ex2 from ring (off-chain)
        if (t + 4 < T)
            oR[t & 3] = __ldcs(reinterpret_cast<const float2*>(ob + (size_t)(t + 4) * S));
        const float2 on = oR[(t + 1) & 3];
        pn0 = ex2f_(on.x * LOG2E_F);
        pn1 = ex2f_(on.y * LOG2E_F);

        // fold an exact 2^-e every 8th step, e = exponent of state 0
        // (broadcast LDS -- uniform reference, no reduction needed)
        float sc = 1.0f;
        const bool fold = (t & 7) == 1;
        if (fold) {
            const float v0ref = v_sm[cb][0];
            const int e = ((__float_as_int(v0ref) >> 23) & 0xFF) - 127;
            L += e;
            sc = __int_as_float((127 - e) << 23);   // exact 2^-e
        }

        // matvec over this thread's 32-i chunk: 16 LDS.64, 4 fma2 chains
        const unsigned long long* V =
            reinterpret_cast<const unsigned long long*>(&v_sm[cb][ich * CH]);
        unsigned long long c0a = 0ull, c0b = 0ull, c1a = 0ull, c1b = 0ull;
#pragma unroll
        for (int k = 0; k < 8; ++k) {
            const unsigned long long va = V[2 * k], vb = V[2 * k + 1];
            fma2_(c0a, va, A0[2 * k]);
            fma2_(c1a, va, A1[2 * k]);
            fma2_(c0b, vb, A0[2 * k + 1]);
            fma2_(c1b, vb, A1[2 * k + 1]);
        }
        float x0, y0, x1, y1;
        upk2(add2_(c0a, c0b), x0, y0);
        upk2(add2_(c1a, c1b), x1, y1);
        float acc0 = x0 + y0;
        float acc1 = x1 + y1;
        // butterfly across the 4 i-chunks (lane^1, lane^2 flip only ich)
        acc0 += __shfl_xor_sync(0xffffffffu, acc0, 1);
        acc1 += __shfl_xor_sync(0xffffffffu, acc1, 1);
        acc0 += __shfl_xor_sync(0xffffffffu, acc0, 2);
        acc1 += __shfl_xor_sync(0xffffffffu, acc1, 2);

        const float un0 = fold ? acc0 * (p0 * sc) : acc0 * p0;
        const float un1 = fold ? acc1 * (p1 * sc) : acc1 * p1;

        if (ich == 0) {
            float2 w; w.x = un0; w.y = un1;
            *reinterpret_cast<float2*>(&v_sm[nb][wslot]) = w;
        }
        __syncthreads();
    }

    // ---- finalize: out[b] = -ln2 * (log2(sum_j v_j) + L) ----
    const int fb = (T - 1) & 1;
    float vv = 0.f;
    if (tid < 128) vv = v_sm[fb][((tid >> 5) * CH) + (tid & 31)];
#pragma unroll
    for (int o = 16; o; o >>= 1) vv += __shfl_xor_sync(0xffffffffu, vv, o);
    if (tid < 128 && (tid & 31) == 0) wsum[tid >> 5] = vv;
    __syncthreads();
    if (tid == 0) {
        const float s = (wsum[0] + wsum[1]) + (wsum[2] + wsum[3]);
        out[b] = -LN2_F * (lg2f_(s) + (float)L);
    }
}

extern "C" void kernel_launch(void* const* d_in, const int* in_sizes, int n_in,
                              void* d_out, int out_size)
{
    const float* obs  = (const float*)d_in[0];   // [B, T, S] f32
    const float* logA = (const float*)d_in[1];   // [S, S]   f32
    float* out = (float*)d_out;                  // [B]      f32

    const int B = out_size;
    const int S = 128;
    const int T = in_sizes[0] / (B * S);

    crf_fwd_kernel<<<B, 256>>>(obs, logA, out, T);
}